// round 16
// baseline (speedup 1.0000x reference)
#include <cuda_runtime.h>

#define HH    1024
#define WW    1024
#define CIN   8
#define COUT  8
#define KS    31
#define PAD   15
#define NFFT  2048
#define NBINS 1025          // Hermitian half: bins 0..1024
#define FS    1088          // padded bin stride (multiple of 16)

// Scratch (static device globals — allocation-guard-safe). ~160 MB total.
__device__ float2 g_S[CIN * HH * FS];          // signal row spectra
__device__ float2 g_W[COUT * CIN * KS * FS];   // weight row spectra
__device__ float2 g_ACC[COUT * HH * FS];       // per-ci chunk of output spectra

// ---------------------------------------------------------------------------
// In-block 2048-point complex FFT, Stockham autosort (no bit reversal).
// 256 threads, ping-pong smem buffers. Twiddle table tw[k] = exp(-2*pi*i*k/2048).
// Returns pointer to the buffer holding the result.
// ---------------------------------------------------------------------------
template <bool INV>
__device__ __forceinline__ float2* fft2048(float2* a, float2* b,
                                           const float2* tw, int tid)
{
    float2* src = a;
    float2* dst = b;
    int Ns = 1;
#pragma unroll 1
    for (int stage = 0; stage < 11; stage++) {
        __syncthreads();
        const int m = 1024 >> stage;          // twiddle index step
#pragma unroll
        for (int q = 0; q < 4; q++) {
            const int j = tid + q * 256;      // butterfly id 0..1023
            const int k = j & (Ns - 1);       // j % Ns
            float2 w = tw[k * m];
            const float wy = INV ? -w.y : w.y;
            const float2 u = src[j];
            const float2 v = src[j + 1024];
            const float tr = v.x * w.x - v.y * wy;
            const float ti = v.x * wy + v.y * w.x;
            const int d = 2 * j - k;          // (j/Ns)*2Ns + k
            dst[d]      = make_float2(u.x + tr, u.y + ti);
            dst[d + Ns] = make_float2(u.x - tr, u.y - ti);
        }
        float2* t = src; src = dst; dst = t;
        Ns <<= 1;
    }
    __syncthreads();
    return src;                                // holds last-written stage
}

__device__ __forceinline__ void fill_twiddles(float2* tw, int tid)
{
    for (int k = tid; k < 1024; k += 256) {
        float s, c;
        __sincosf((float)k * (-6.28318530717958647692f / 2048.f), &s, &c);
        tw[k] = make_float2(c, s);
    }
}

// ---------------------------------------------------------------------------
// Kernel A: forward FFT of each signal row (zero-padded to 2048).
// grid (HH, CIN), 256 threads.
// ---------------------------------------------------------------------------
__global__ __launch_bounds__(256)
void fft_sig_kernel(const float* __restrict__ sig)
{
    __shared__ float2 bufa[NFFT], bufb[NFFT], tw[1024];
    const int tid = threadIdx.x;
    const int y  = blockIdx.x;
    const int ci = blockIdx.y;

    fill_twiddles(tw, tid);
    const float* row = sig + (ci * HH + y) * WW;
    for (int i = tid; i < NFFT; i += 256)
        bufa[i] = make_float2(i < WW ? row[i] : 0.f, 0.f);

    float2* r = fft2048<false>(bufa, bufb, tw, tid);

    float2* o = g_S + (ci * HH + y) * FS;
    for (int f = tid; f < FS; f += 256)
        o[f] = (f < NBINS) ? r[f] : make_float2(0.f, 0.f);
}

// ---------------------------------------------------------------------------
// Kernel B: forward FFT of each weight row (31 taps zero-padded to 2048).
// grid (KS, CIN, COUT), 256 threads.
// ---------------------------------------------------------------------------
__global__ __launch_bounds__(256)
void fft_w_kernel(const float* __restrict__ w)
{
    __shared__ float2 bufa[NFFT], bufb[NFFT], tw[1024];
    const int tid = threadIdx.x;
    const int ky = blockIdx.x;
    const int ci = blockIdx.y;
    const int co = blockIdx.z;

    fill_twiddles(tw, tid);
    const float* row = w + ((co * CIN + ci) * KS + ky) * KS;
    for (int i = tid; i < NFFT; i += 256)
        bufa[i] = make_float2(i < KS ? row[i] : 0.f, 0.f);

    float2* r = fft2048<false>(bufa, bufb, tw, tid);

    float2* o = g_W + ((co * CIN + ci) * KS + ky) * FS;
    for (int f = tid; f < FS; f += 256)
        o[f] = (f < NBINS) ? r[f] : make_float2(0.f, 0.f);
}

// ---------------------------------------------------------------------------
// Kernel C (hot): frequency-domain accumulation over ky for one ci.
//   g_ACC[co][y][f] = sum_ky g_S[ci][y+ky-15][f] * conj(g_W[co][ci][ky][f])
// grid (FS/16, HH/32), block (16,16). smem 39.8 KB.
// ---------------------------------------------------------------------------
__global__ __launch_bounds__(256, 2)
void accum_kernel(int ci)
{
    __shared__ float2 sS[62][17];              // padded to kill bank conflicts
    __shared__ float2 sW[COUT][KS][16];

    const int tx  = threadIdx.x;               // f within tile (0..15)
    const int ty  = threadIdx.y;               // y-group (0..15), 2 y each
    const int tid = ty * 16 + tx;
    const int f0  = blockIdx.x * 16;
    const int y0  = blockIdx.y * 32;

    // S rows y0-15 .. y0+46 (zero outside image)
    for (int idx = tid; idx < 62 * 16; idx += 256) {
        const int r = idx >> 4, f = idx & 15;
        const int gy = y0 + r - PAD;
        float2 v = make_float2(0.f, 0.f);
        if ((unsigned)gy < (unsigned)HH)
            v = g_S[(ci * HH + gy) * FS + f0 + f];
        sS[r][f] = v;
    }
    // W spectra for all 8 co, 31 ky
    for (int idx = tid; idx < COUT * KS * 16; idx += 256) {
        const int f  = idx & 15;
        const int t  = idx >> 4;
        const int ky = t % KS;
        const int co = t / KS;
        sW[co][ky][f] = g_W[((co * CIN + ci) * KS + ky) * FS + f0 + f];
    }
    __syncthreads();

    float2 acc[2][COUT];
#pragma unroll
    for (int yy = 0; yy < 2; yy++)
#pragma unroll
        for (int co = 0; co < COUT; co++) acc[yy][co] = make_float2(0.f, 0.f);

#pragma unroll 1
    for (int ky = 0; ky < KS; ky++) {
        const float2 s0 = sS[ty * 2 + 0 + ky][tx];
        const float2 s1 = sS[ty * 2 + 1 + ky][tx];
#pragma unroll
        for (int co = 0; co < COUT; co++) {
            const float2 w = sW[co][ky][tx];
            // s * conj(w)
            acc[0][co].x += s0.x * w.x + s0.y * w.y;
            acc[0][co].y += s0.y * w.x - s0.x * w.y;
            acc[1][co].x += s1.x * w.x + s1.y * w.y;
            acc[1][co].y += s1.y * w.x - s1.x * w.y;
        }
    }

#pragma unroll
    for (int co = 0; co < COUT; co++)
#pragma unroll
        for (int yy = 0; yy < 2; yy++)
            g_ACC[(co * HH + y0 + ty * 2 + yy) * FS + f0 + tx] = acc[yy][co];
}

// ---------------------------------------------------------------------------
// Kernel D: Hermitian-mirror + inverse FFT per output row, +bias, store.
// grid (HH, COUT) per ci, 256 threads.
// ---------------------------------------------------------------------------
__global__ __launch_bounds__(256)
void ifft_kernel(const float* __restrict__ bias, float* __restrict__ out, int ci)
{
    __shared__ float2 bufa[NFFT], bufb[NFFT], tw[1024];
    const int tid = threadIdx.x;
    const int y  = blockIdx.x;
    const int co = blockIdx.y;

    fill_twiddles(tw, tid);
    const float2* a = g_ACC + (co * HH + y) * FS;
    for (int i = tid; i < NFFT; i += 256) {
        float2 v;
        if (i <= 1024) {
            v = a[i];
        } else {
            const float2 t = a[NFFT - i];
            v = make_float2(t.x, -t.y);
        }
        bufa[i] = v;
    }

    float2* r = fft2048<true>(bufa, bufb, tw, tid);

    const float b = bias[ci];
    float* op = out + ((co * CIN + ci) * HH + y) * WW;
    for (int x = tid; x < WW; x += 256)
        op[x] = r[(x + NFFT - PAD) & (NFFT - 1)].x * (1.f / NFFT) + b;
}

// ---------------------------------------------------------------------------
extern "C" void kernel_launch(void* const* d_in, const int* in_sizes, int n_in,
                              void* d_out, int out_size)
{
    const float* sig  = (const float*)d_in[0];   // [1,8,1024,1024]
    const float* w    = (const float*)d_in[1];   // [8,8,31,31]
    const float* bias = (const float*)d_in[2];   // [8]
    float* out = (float*)d_out;                  // [8,8,1024,1024] (co,ci,y,x)

    fft_sig_kernel<<<dim3(HH, CIN), 256>>>(sig);
    fft_w_kernel<<<dim3(KS, CIN, COUT), 256>>>(w);

    for (int ci = 0; ci < CIN; ci++) {
        accum_kernel<<<dim3(FS / 16, HH / 32), dim3(16, 16)>>>(ci);
        ifft_kernel<<<dim3(HH, COUT), 256>>>(bias, out, ci);
    }
}